// round 1
// baseline (speedup 1.0000x reference)
#include <cuda_runtime.h>

#define Bn  4
#define Sn  1024
#define DMn 1024
#define Hn  16
#define DKn 64

// Scratch (allocation-free rule: __device__ globals)
__device__ float g_Q[(size_t)Bn * Hn * Sn * DKn];   // [b,h,s,k]
__device__ float g_K[(size_t)Bn * Hn * Sn * DKn];   // [b,h,s,k]
__device__ float g_V[(size_t)Bn * Hn * Sn * DKn];   // [b,h,s,v]
__device__ float g_Z[(size_t)Bn * Sn * Hn * DKn];   // [b,s,h*64+v]  (concat layout)

// ---------------------------------------------------------------------------
// Kernel 1: QKV projection. grid = (S/128, B*H, 3), block = 256.
// Per (b,h): [1024 x 1024] @ [1024 x 64] GEMM, tile 128x64, BK=16, 8x4 micro.
// ---------------------------------------------------------------------------
__global__ __launch_bounds__(256) void qkv_proj_kernel(
    const float* __restrict__ X,
    const float* __restrict__ Wq, const float* __restrict__ bq,
    const float* __restrict__ Wk, const float* __restrict__ bk,
    const float* __restrict__ Wv, const float* __restrict__ bv)
{
    const float* W; const float* bias; float* out;
    int sel = blockIdx.z;
    if (sel == 0)      { W = Wq; bias = bq; out = g_Q; }
    else if (sel == 1) { W = Wk; bias = bk; out = g_K; }
    else               { W = Wv; bias = bv; out = g_V; }

    int bh = blockIdx.y;
    int b  = bh >> 4;
    int h  = bh & 15;
    int m0 = blockIdx.x * 128;

    const float* A  = X + (size_t)b * Sn * DMn;        // rows m0.., stride 1024
    const float* Bm = W + (size_t)h * DMn * DKn;       // [1024,64] row-major
    float*       O  = out + ((size_t)bh * Sn + m0) * DKn;

    __shared__ float As[16 * 132];   // transposed [kk][m], padded stride 132
    __shared__ float Bs[16 * 64];    // [kk][n]

    int tid = threadIdx.x;
    int ty  = tid >> 4;   // 0..15 -> rows ty*8..ty*8+7
    int tx  = tid & 15;   // 0..15 -> cols tx*4..tx*4+3

    float acc[8][4];
    #pragma unroll
    for (int i = 0; i < 8; i++)
        #pragma unroll
        for (int j = 0; j < 4; j++) acc[i][j] = 0.f;

    for (int kt = 0; kt < DMn; kt += 16) {
        #pragma unroll
        for (int it = 0; it < 2; it++) {
            int idx = it * 256 + tid;          // 0..511
            int row = idx >> 2;                // 0..127
            int cq  = idx & 3;                 // 0..3
            float4 v = *reinterpret_cast<const float4*>(
                &A[(size_t)(m0 + row) * DMn + kt + cq * 4]);
            As[(cq * 4 + 0) * 132 + row] = v.x;
            As[(cq * 4 + 1) * 132 + row] = v.y;
            As[(cq * 4 + 2) * 132 + row] = v.z;
            As[(cq * 4 + 3) * 132 + row] = v.w;
        }
        {
            int d  = tid >> 4;                 // 0..15
            int c4 = tid & 15;                 // 0..15
            *reinterpret_cast<float4*>(&Bs[d * 64 + c4 * 4]) =
                *reinterpret_cast<const float4*>(&Bm[(size_t)(kt + d) * DKn + c4 * 4]);
        }
        __syncthreads();
        #pragma unroll
        for (int kk = 0; kk < 16; kk++) {
            float4 a0 = *reinterpret_cast<float4*>(&As[kk * 132 + ty * 8]);
            float4 a1 = *reinterpret_cast<float4*>(&As[kk * 132 + ty * 8 + 4]);
            float4 b4 = *reinterpret_cast<float4*>(&Bs[kk * 64 + tx * 4]);
            float a[8] = {a0.x, a0.y, a0.z, a0.w, a1.x, a1.y, a1.z, a1.w};
            float bb[4] = {b4.x, b4.y, b4.z, b4.w};
            #pragma unroll
            for (int i = 0; i < 8; i++)
                #pragma unroll
                for (int j = 0; j < 4; j++)
                    acc[i][j] += a[i] * bb[j];
        }
        __syncthreads();
    }

    float4 bv4 = *reinterpret_cast<const float4*>(&bias[h * 64 + tx * 4]);
    #pragma unroll
    for (int i = 0; i < 8; i++) {
        int s = ty * 8 + i;
        float4 v;
        v.x = acc[i][0] + bv4.x;
        v.y = acc[i][1] + bv4.y;
        v.z = acc[i][2] + bv4.z;
        v.w = acc[i][3] + bv4.w;
        *reinterpret_cast<float4*>(&O[(size_t)s * DKn + tx * 4]) = v;
    }
}

// ---------------------------------------------------------------------------
// Kernel 2: flash attention. grid = (S/64, H, B), block = 256.
// Q-tile 64 rows, key tiles of 64, online softmax. smem = 3 x 16KB = 48KB.
// KP buffer holds K^T during score GEMM, then is reused for P (natural [r][k]).
// ---------------------------------------------------------------------------
__global__ __launch_bounds__(256) void attn_kernel()
{
    int q0 = blockIdx.x * 64;
    int h  = blockIdx.y;
    int b  = blockIdx.z;
    int bh = b * Hn + h;

    const float* Qg = g_Q + (size_t)bh * Sn * DKn;
    const float* Kg = g_K + (size_t)bh * Sn * DKn;
    const float* Vg = g_V + (size_t)bh * Sn * DKn;

    __shared__ float Qs[64 * 64];   // Q^T: [d][r]
    __shared__ float KP[64 * 64];   // K^T: [d][c], later P: [r][k]
    __shared__ float Vs[64 * 64];   // V:   [k][v]

    int tid = threadIdx.x;
    int ty  = tid >> 4;   // rows r = ty*4+i
    int tx  = tid & 15;   // cols c = tx*4+j

    // Load Q tile transposed (store pattern chosen conflict-free: row = idx&63)
    #pragma unroll
    for (int it = 0; it < 4; it++) {
        int idx = it * 256 + tid;
        int row = idx & 63;
        int c4  = idx >> 6;
        float4 v = *reinterpret_cast<const float4*>(
            &Qg[(size_t)(q0 + row) * DKn + c4 * 4]);
        Qs[(c4 * 4 + 0) * 64 + row] = v.x;
        Qs[(c4 * 4 + 1) * 64 + row] = v.y;
        Qs[(c4 * 4 + 2) * 64 + row] = v.z;
        Qs[(c4 * 4 + 3) * 64 + row] = v.w;
    }

    float m_i[4], l_i[4], o[4][4];
    #pragma unroll
    for (int i = 0; i < 4; i++) {
        m_i[i] = -3.0e38f;
        l_i[i] = 0.f;
        #pragma unroll
        for (int j = 0; j < 4; j++) o[i][j] = 0.f;
    }

    for (int t = 0; t < Sn; t += 64) {
        __syncthreads();   // prior PV reads of KP/Vs done
        #pragma unroll
        for (int it = 0; it < 4; it++) {
            int idx = it * 256 + tid;
            int row = idx & 63;
            int c4  = idx >> 6;
            float4 v = *reinterpret_cast<const float4*>(
                &Kg[(size_t)(t + row) * DKn + c4 * 4]);
            KP[(c4 * 4 + 0) * 64 + row] = v.x;
            KP[(c4 * 4 + 1) * 64 + row] = v.y;
            KP[(c4 * 4 + 2) * 64 + row] = v.z;
            KP[(c4 * 4 + 3) * 64 + row] = v.w;
            float4 w = *reinterpret_cast<const float4*>(&Vg[(size_t)t * DKn + idx * 4]);
            *reinterpret_cast<float4*>(&Vs[idx * 4]) = w;
        }
        __syncthreads();

        // S = (Q K^T) * 0.125
        float sacc[4][4];
        #pragma unroll
        for (int i = 0; i < 4; i++)
            #pragma unroll
            for (int j = 0; j < 4; j++) sacc[i][j] = 0.f;

        #pragma unroll 4
        for (int d = 0; d < 64; d++) {
            float4 a4 = *reinterpret_cast<float4*>(&Qs[d * 64 + ty * 4]);
            float4 b4 = *reinterpret_cast<float4*>(&KP[d * 64 + tx * 4]);
            float a[4] = {a4.x, a4.y, a4.z, a4.w};
            float bb[4] = {b4.x, b4.y, b4.z, b4.w};
            #pragma unroll
            for (int i = 0; i < 4; i++)
                #pragma unroll
                for (int j = 0; j < 4; j++)
                    sacc[i][j] += a[i] * bb[j];
        }

        // Online softmax (row stats reduced across the 16 lanes of a half-warp)
        float p[4][4];
        #pragma unroll
        for (int i = 0; i < 4; i++) {
            float rm = sacc[i][0];
            #pragma unroll
            for (int j = 1; j < 4; j++) rm = fmaxf(rm, sacc[i][j]);
            rm *= 0.125f;
            #pragma unroll
            for (int off = 1; off < 16; off <<= 1)
                rm = fmaxf(rm, __shfl_xor_sync(0xffffffffu, rm, off));
            float nm   = fmaxf(m_i[i], rm);
            float corr = __expf(m_i[i] - nm);
            m_i[i] = nm;
            float rs = 0.f;
            #pragma unroll
            for (int j = 0; j < 4; j++) {
                p[i][j] = __expf(sacc[i][j] * 0.125f - nm);
                rs += p[i][j];
            }
            #pragma unroll
            for (int off = 1; off < 16; off <<= 1)
                rs += __shfl_xor_sync(0xffffffffu, rs, off);
            l_i[i] = l_i[i] * corr + rs;
            #pragma unroll
            for (int j = 0; j < 4; j++) o[i][j] *= corr;
        }

        __syncthreads();   // all score reads of KP done before overwriting with P
        #pragma unroll
        for (int i = 0; i < 4; i++) {
            float4 v = make_float4(p[i][0], p[i][1], p[i][2], p[i][3]);
            *reinterpret_cast<float4*>(&KP[(ty * 4 + i) * 64 + tx * 4]) = v;
        }
        __syncthreads();

        // O += P @ V   (k unrolled by 4 so a-frags are float4)
        #pragma unroll 2
        for (int k = 0; k < 64; k += 4) {
            float av[4][4];
            #pragma unroll
            for (int i = 0; i < 4; i++) {
                float4 a4 = *reinterpret_cast<float4*>(&KP[(ty * 4 + i) * 64 + k]);
                av[i][0] = a4.x; av[i][1] = a4.y; av[i][2] = a4.z; av[i][3] = a4.w;
            }
            #pragma unroll
            for (int kk = 0; kk < 4; kk++) {
                float4 b4 = *reinterpret_cast<float4*>(&Vs[(k + kk) * 64 + tx * 4]);
                float bb[4] = {b4.x, b4.y, b4.z, b4.w};
                #pragma unroll
                for (int i = 0; i < 4; i++)
                    #pragma unroll
                    for (int j = 0; j < 4; j++)
                        o[i][j] += av[i][kk] * bb[j];
            }
        }
    }

    // Write to concat layout Zc[b, s, h*64+v]
    #pragma unroll
    for (int i = 0; i < 4; i++) {
        float inv = 1.0f / l_i[i];
        int r = q0 + ty * 4 + i;
        float4 v = make_float4(o[i][0] * inv, o[i][1] * inv,
                               o[i][2] * inv, o[i][3] * inv);
        *reinterpret_cast<float4*>(
            &g_Z[((size_t)b * Sn + r) * (Hn * DKn) + h * DKn + tx * 4]) = v;
    }
}

// ---------------------------------------------------------------------------
// Kernel 3: output projection + bias + residual.
// C[4096,1024] = Zc[4096,1024] @ Wo[1024,1024] + bo + X.  grid = (16, 32).
// ---------------------------------------------------------------------------
__global__ __launch_bounds__(256) void out_proj_kernel(
    const float* __restrict__ Wo, const float* __restrict__ bo,
    const float* __restrict__ X, float* __restrict__ out)
{
    int n0 = blockIdx.x * 64;
    int m0 = blockIdx.y * 128;

    __shared__ float As[16 * 132];
    __shared__ float Bs[16 * 64];

    int tid = threadIdx.x;
    int ty  = tid >> 4;
    int tx  = tid & 15;

    float acc[8][4];
    #pragma unroll
    for (int i = 0; i < 8; i++)
        #pragma unroll
        for (int j = 0; j < 4; j++) acc[i][j] = 0.f;

    const int N = Hn * DKn;   // 1024 (= D_MODEL)

    for (int kt = 0; kt < N; kt += 16) {
        #pragma unroll
        for (int it = 0; it < 2; it++) {
            int idx = it * 256 + tid;
            int row = idx >> 2;
            int cq  = idx & 3;
            float4 v = *reinterpret_cast<const float4*>(
                &g_Z[(size_t)(m0 + row) * N + kt + cq * 4]);
            As[(cq * 4 + 0) * 132 + row] = v.x;
            As[(cq * 4 + 1) * 132 + row] = v.y;
            As[(cq * 4 + 2) * 132 + row] = v.z;
            As[(cq * 4 + 3) * 132 + row] = v.w;
        }
        {
            int d  = tid >> 4;
            int c4 = tid & 15;
            *reinterpret_cast<float4*>(&Bs[d * 64 + c4 * 4]) =
                *reinterpret_cast<const float4*>(&Wo[(size_t)(kt + d) * DMn + n0 + c4 * 4]);
        }
        __syncthreads();
        #pragma unroll
        for (int kk = 0; kk < 16; kk++) {
            float4 a0 = *reinterpret_cast<float4*>(&As[kk * 132 + ty * 8]);
            float4 a1 = *reinterpret_cast<float4*>(&As[kk * 132 + ty * 8 + 4]);
            float4 b4 = *reinterpret_cast<float4*>(&Bs[kk * 64 + tx * 4]);
            float a[8] = {a0.x, a0.y, a0.z, a0.w, a1.x, a1.y, a1.z, a1.w};
            float bb[4] = {b4.x, b4.y, b4.z, b4.w};
            #pragma unroll
            for (int i = 0; i < 8; i++)
                #pragma unroll
                for (int j = 0; j < 4; j++)
                    acc[i][j] += a[i] * bb[j];
        }
        __syncthreads();
    }

    float4 bv4 = *reinterpret_cast<const float4*>(&bo[n0 + tx * 4]);
    #pragma unroll
    for (int i = 0; i < 8; i++) {
        int m = m0 + ty * 8 + i;
        float4 xr = *reinterpret_cast<const float4*>(&X[(size_t)m * DMn + n0 + tx * 4]);
        float4 v;
        v.x = acc[i][0] + bv4.x + xr.x;
        v.y = acc[i][1] + bv4.y + xr.y;
        v.z = acc[i][2] + bv4.z + xr.z;
        v.w = acc[i][3] + bv4.w + xr.w;
        *reinterpret_cast<float4*>(&out[(size_t)m * DMn + n0 + tx * 4]) = v;
    }
}

// ---------------------------------------------------------------------------
extern "C" void kernel_launch(void* const* d_in, const int* in_sizes, int n_in,
                              void* d_out, int out_size)
{
    const float* X  = (const float*)d_in[0];
    const float* Wk = (const float*)d_in[1];
    const float* bk = (const float*)d_in[2];
    const float* Wq = (const float*)d_in[3];
    const float* bq = (const float*)d_in[4];
    const float* Wv = (const float*)d_in[5];
    const float* bv = (const float*)d_in[6];
    const float* Wo = (const float*)d_in[7];
    const float* bo = (const float*)d_in[8];
    float* out = (float*)d_out;

    qkv_proj_kernel<<<dim3(Sn / 128, Bn * Hn, 3), 256>>>(X, Wq, bq, Wk, bk, Wv, bv);
    attn_kernel<<<dim3(Sn / 64, Hn, Bn), 256>>>();
    out_proj_kernel<<<dim3(DMn / 64, (Bn * Sn) / 128), 256>>>(Wo, bo, X, out);
}

// round 3
// speedup vs baseline: 1.5720x; 1.5720x over previous
#include <cuda_runtime.h>
#include <cstdint>

#define Bn  4
#define Sn  1024
#define DMn 1024
#define Hn  16
#define DKn 64

// Scratch (allocation-free rule: __device__ globals)
__device__ float g_Q[(size_t)Bn * Hn * Sn * DKn];   // [b,h,s,k]
__device__ float g_K[(size_t)Bn * Hn * Sn * DKn];
__device__ float g_V[(size_t)Bn * Hn * Sn * DKn];
__device__ float g_Z[(size_t)Bn * Sn * Hn * DKn];   // [b,s,h*64+v]
// Transposed (K-major) weights: rows n (0..4095), cols d (0..1023), tf32-rounded
//   n in [0,1024): Q | [1024,2048): K | [2048,3072): V | [3072,4096): Wo col
__device__ float g_Wt[(size_t)4096 * 1024];

__device__ __forceinline__ float to_tf32(float x) {
    uint32_t u;
    asm("cvt.rna.tf32.f32 %0, %1;" : "=r"(u) : "f"(x));
    return __uint_as_float(u);
}

__device__ __forceinline__ void mma_tf32(float* c, const uint32_t* a, const uint32_t* b) {
    asm volatile(
        "mma.sync.aligned.m16n8k8.row.col.f32.tf32.tf32.f32 "
        "{%0,%1,%2,%3}, {%4,%5,%6,%7}, {%8,%9}, {%0,%1,%2,%3};"
        : "+f"(c[0]), "+f"(c[1]), "+f"(c[2]), "+f"(c[3])
        : "r"(a[0]), "r"(a[1]), "r"(a[2]), "r"(a[3]), "r"(b[0]), "r"(b[1]));
}

// ---------------------------------------------------------------------------
// Kernel 0: pack weights transposed (K-major) + tf32-round.  grid=(128,32),256t
// ---------------------------------------------------------------------------
__global__ __launch_bounds__(256) void transpose_w_kernel(
    const float* __restrict__ Wq, const float* __restrict__ Wk,
    const float* __restrict__ Wv, const float* __restrict__ Wo)
{
    __shared__ float t[32][33];
    int n0 = blockIdx.x * 32;
    int d0 = blockIdx.y * 32;
    int r  = n0 >> 10;
    int tid = threadIdx.x;

    #pragma unroll
    for (int p = 0; p < 4; p++) {
        int idx = p * 256 + tid;
        int dl  = idx >> 5;     // d offset
        int j   = idx & 31;     // n offset
        int d   = d0 + dl;
        float v;
        if (r < 3) {
            int hh = (n0 >> 6) & 15;
            int k0 = n0 & 63;
            const float* W = (r == 0) ? Wq : (r == 1) ? Wk : Wv;
            v = W[(size_t)hh * 65536 + (size_t)d * 64 + k0 + j];
        } else {
            v = Wo[(size_t)d * 1024 + (n0 - 3072) + j];
        }
        t[dl][j] = v;
    }
    __syncthreads();
    #pragma unroll
    for (int p = 0; p < 4; p++) {
        int idx = p * 256 + tid;
        int nl  = idx >> 5;
        int dd  = idx & 31;
        g_Wt[(size_t)(n0 + nl) * 1024 + d0 + dd] = to_tf32(t[dd][nl]);
    }
}

// ---------------------------------------------------------------------------
// tf32 mma.sync GEMM: C[4096, NG] = A[4096,1024] @ Wt[NG,1024]^T
// Tile BM=128 x BN=128, BK=32, 256 threads (8 warps, 2Mx4N), warp = 64x32.
// MODE 0: fused QKV (NG=3072) with bias + scatter to g_Q/g_K/g_V.
// MODE 1: out-proj (NG=1024) with bias + residual into d_out.
// ---------------------------------------------------------------------------
#define BKp 36

template <int MODE>
__global__ __launch_bounds__(256) void gemm_mma_kernel(
    const float* __restrict__ Ain,
    const float* __restrict__ b0, const float* __restrict__ b1,
    const float* __restrict__ b2,
    const float* __restrict__ Xres, float* __restrict__ Out)
{
    __shared__ float As[128 * BKp];
    __shared__ float Bs[128 * BKp];

    const int tid  = threadIdx.x;
    const int wid  = tid >> 5;
    const int lane = tid & 31;
    const int grp  = lane >> 2;   // 0..7
    const int tig  = lane & 3;    // 0..3
    const int wm   = wid & 1;     // 2 warps in M
    const int wn   = wid >> 1;    // 4 warps in N
    const int n0   = blockIdx.x * 128;
    const int m0   = blockIdx.y * 128;

    const float* A  = (MODE == 0) ? Ain : g_Z;
    const float* Bw = (MODE == 0) ? g_Wt : (g_Wt + (size_t)3072 * 1024);

    float acc[4][4][4];
    #pragma unroll
    for (int mt = 0; mt < 4; mt++)
        #pragma unroll
        for (int nt = 0; nt < 4; nt++)
            #pragma unroll
            for (int e = 0; e < 4; e++) acc[mt][nt][e] = 0.f;

    for (int kt = 0; kt < 1024; kt += 32) {
        // Stage A (tf32-convert) and B tiles: 128 rows x 32 k each
        #pragma unroll
        for (int it = 0; it < 4; it++) {
            int idx = it * 256 + tid;     // 0..1023
            int row = idx >> 3;           // 0..127
            int c4  = idx & 7;            // 0..7
            float4 va = *reinterpret_cast<const float4*>(
                &A[(size_t)(m0 + row) * 1024 + kt + c4 * 4]);
            va.x = to_tf32(va.x); va.y = to_tf32(va.y);
            va.z = to_tf32(va.z); va.w = to_tf32(va.w);
            *reinterpret_cast<float4*>(&As[row * BKp + c4 * 4]) = va;
            float4 vb = *reinterpret_cast<const float4*>(
                &Bw[(size_t)(n0 + row) * 1024 + kt + c4 * 4]);
            *reinterpret_cast<float4*>(&Bs[row * BKp + c4 * 4]) = vb;
        }
        __syncthreads();

        #pragma unroll
        for (int ks = 0; ks < 4; ks++) {
            const int k = ks * 8;
            uint32_t bf[4][2];
            #pragma unroll
            for (int nt = 0; nt < 4; nt++) {
                int n = wn * 32 + nt * 8 + grp;
                bf[nt][0] = __float_as_uint(Bs[n * BKp + k + tig]);
                bf[nt][1] = __float_as_uint(Bs[n * BKp + k + tig + 4]);
            }
            #pragma unroll
            for (int mt = 0; mt < 4; mt++) {
                int r = wm * 64 + mt * 16 + grp;
                uint32_t af[4];
                af[0] = __float_as_uint(As[r * BKp + k + tig]);
                af[1] = __float_as_uint(As[(r + 8) * BKp + k + tig]);
                af[2] = __float_as_uint(As[r * BKp + k + tig + 4]);
                af[3] = __float_as_uint(As[(r + 8) * BKp + k + tig + 4]);
                #pragma unroll
                for (int nt = 0; nt < 4; nt++)
                    mma_tf32(acc[mt][nt], af, bf[nt]);
            }
        }
        __syncthreads();
    }

    // Epilogue: direct fragment stores (float2, full 32B sectors per quad)
    #pragma unroll
    for (int nt = 0; nt < 4; nt++) {
        int n_base = n0 + wn * 32 + nt * 8;        // 8-aligned, uniform per warp
        int ncol   = 2 * tig;                      // 0,2,4,6 within tile
        if (MODE == 0) {
            int sel = n_base >> 10;
            int hh  = (n_base >> 6) & 15;
            int kk  = (n_base & 63) + ncol;
            const float* bias = (sel == 0) ? b0 : (sel == 1) ? b1 : b2;
            float* dst = (sel == 0) ? g_Q : (sel == 1) ? g_K : g_V;
            float bv0 = bias[hh * 64 + kk];
            float bv1 = bias[hh * 64 + kk + 1];
            #pragma unroll
            for (int mt = 0; mt < 4; mt++) {
                int r = m0 + wm * 64 + mt * 16 + grp;
                #pragma unroll
                for (int hrow = 0; hrow < 2; hrow++) {
                    int m  = r + hrow * 8;
                    int bb = m >> 10, ss = m & 1023;
                    float2 v;
                    v.x = acc[mt][nt][hrow * 2 + 0] + bv0;
                    v.y = acc[mt][nt][hrow * 2 + 1] + bv1;
                    *reinterpret_cast<float2*>(
                        &dst[((size_t)(bb * 16 + hh) * 1024 + ss) * 64 + kk]) = v;
                }
            }
        } else {
            int n  = n_base + ncol;
            float bv0 = b0[n], bv1 = b0[n + 1];
            #pragma unroll
            for (int mt = 0; mt < 4; mt++) {
                int r = m0 + wm * 64 + mt * 16 + grp;
                #pragma unroll
                for (int hrow = 0; hrow < 2; hrow++) {
                    int m = r + hrow * 8;
                    float2 xr = *reinterpret_cast<const float2*>(
                        &Xres[(size_t)m * 1024 + n]);
                    float2 v;
                    v.x = acc[mt][nt][hrow * 2 + 0] + bv0 + xr.x;
                    v.y = acc[mt][nt][hrow * 2 + 1] + bv1 + xr.y;
                    *reinterpret_cast<float2*>(&Out[(size_t)m * 1024 + n]) = v;
                }
            }
        }
    }
}

// ---------------------------------------------------------------------------
// Kernel 2: flash attention (SIMT, unchanged). grid = (S/64, H, B), block 256.
// ---------------------------------------------------------------------------
__global__ __launch_bounds__(256) void attn_kernel()
{
    int q0 = blockIdx.x * 64;
    int h  = blockIdx.y;
    int b  = blockIdx.z;
    int bh = b * Hn + h;

    const float* Qg = g_Q + (size_t)bh * Sn * DKn;
    const float* Kg = g_K + (size_t)bh * Sn * DKn;
    const float* Vg = g_V + (size_t)bh * Sn * DKn;

    __shared__ float Qs[64 * 64];
    __shared__ float KP[64 * 64];
    __shared__ float Vs[64 * 64];

    int tid = threadIdx.x;
    int ty  = tid >> 4;
    int tx  = tid & 15;

    #pragma unroll
    for (int it = 0; it < 4; it++) {
        int idx = it * 256 + tid;
        int row = idx & 63;
        int c4  = idx >> 6;
        float4 v = *reinterpret_cast<const float4*>(
            &Qg[(size_t)(q0 + row) * DKn + c4 * 4]);
        Qs[(c4 * 4 + 0) * 64 + row] = v.x;
        Qs[(c4 * 4 + 1) * 64 + row] = v.y;
        Qs[(c4 * 4 + 2) * 64 + row] = v.z;
        Qs[(c4 * 4 + 3) * 64 + row] = v.w;
    }

    float m_i[4], l_i[4], o[4][4];
    #pragma unroll
    for (int i = 0; i < 4; i++) {
        m_i[i] = -3.0e38f;
        l_i[i] = 0.f;
        #pragma unroll
        for (int j = 0; j < 4; j++) o[i][j] = 0.f;
    }

    for (int t = 0; t < Sn; t += 64) {
        __syncthreads();
        #pragma unroll
        for (int it = 0; it < 4; it++) {
            int idx = it * 256 + tid;
            int row = idx & 63;
            int c4  = idx >> 6;
            float4 v = *reinterpret_cast<const float4*>(
                &Kg[(size_t)(t + row) * DKn + c4 * 4]);
            KP[(c4 * 4 + 0) * 64 + row] = v.x;
            KP[(c4 * 4 + 1) * 64 + row] = v.y;
            KP[(c4 * 4 + 2) * 64 + row] = v.z;
            KP[(c4 * 4 + 3) * 64 + row] = v.w;
            float4 w = *reinterpret_cast<const float4*>(&Vg[(size_t)t * DKn + idx * 4]);
            *reinterpret_cast<float4*>(&Vs[idx * 4]) = w;
        }
        __syncthreads();

        float sacc[4][4];
        #pragma unroll
        for (int i = 0; i < 4; i++)
            #pragma unroll
            for (int j = 0; j < 4; j++) sacc[i][j] = 0.f;

        #pragma unroll 4
        for (int d = 0; d < 64; d++) {
            float4 a4 = *reinterpret_cast<float4*>(&Qs[d * 64 + ty * 4]);
            float4 b4 = *reinterpret_cast<float4*>(&KP[d * 64 + tx * 4]);
            float a[4] = {a4.x, a4.y, a4.z, a4.w};
            float bb[4] = {b4.x, b4.y, b4.z, b4.w};
            #pragma unroll
            for (int i = 0; i < 4; i++)
                #pragma unroll
                for (int j = 0; j < 4; j++)
                    sacc[i][j] += a[i] * bb[j];
        }

        float p[4][4];
        #pragma unroll
        for (int i = 0; i < 4; i++) {
            float rm = sacc[i][0];
            #pragma unroll
            for (int j = 1; j < 4; j++) rm = fmaxf(rm, sacc[i][j]);
            rm *= 0.125f;
            #pragma unroll
            for (int off = 1; off < 16; off <<= 1)
                rm = fmaxf(rm, __shfl_xor_sync(0xffffffffu, rm, off));
            float nm   = fmaxf(m_i[i], rm);
            float corr = __expf(m_i[i] - nm);
            m_i[i] = nm;
            float rs = 0.f;
            #pragma unroll
            for (int j = 0; j < 4; j++) {
                p[i][j] = __expf(sacc[i][j] * 0.125f - nm);
                rs += p[i][j];
            }
            #pragma unroll
            for (int off = 1; off < 16; off <<= 1)
                rs += __shfl_xor_sync(0xffffffffu, rs, off);
            l_i[i] = l_i[i] * corr + rs;
            #pragma unroll
            for (int j = 0; j < 4; j++) o[i][j] *= corr;
        }

        __syncthreads();
        #pragma unroll
        for (int i = 0; i < 4; i++) {
            float4 v = make_float4(p[i][0], p[i][1], p[i][2], p[i][3]);
            *reinterpret_cast<float4*>(&KP[(ty * 4 + i) * 64 + tx * 4]) = v;
        }
        __syncthreads();

        #pragma unroll 2
        for (int k = 0; k < 64; k += 4) {
            float av[4][4];
            #pragma unroll
            for (int i = 0; i < 4; i++) {
                float4 a4 = *reinterpret_cast<float4*>(&KP[(ty * 4 + i) * 64 + k]);
                av[i][0] = a4.x; av[i][1] = a4.y; av[i][2] = a4.z; av[i][3] = a4.w;
            }
            #pragma unroll
            for (int kk = 0; kk < 4; kk++) {
                float4 b4 = *reinterpret_cast<float4*>(&Vs[(k + kk) * 64 + tx * 4]);
                float bb[4] = {b4.x, b4.y, b4.z, b4.w};
                #pragma unroll
                for (int i = 0; i < 4; i++)
                    #pragma unroll
                    for (int j = 0; j < 4; j++)
                        o[i][j] += av[i][kk] * bb[j];
            }
        }
    }

    #pragma unroll
    for (int i = 0; i < 4; i++) {
        float inv = 1.0f / l_i[i];
        int r = q0 + ty * 4 + i;
        float4 v = make_float4(o[i][0] * inv, o[i][1] * inv,
                               o[i][2] * inv, o[i][3] * inv);
        *reinterpret_cast<float4*>(
            &g_Z[((size_t)b * Sn + r) * (Hn * DKn) + h * DKn + tx * 4]) = v;
    }
}

// ---------------------------------------------------------------------------
extern "C" void kernel_launch(void* const* d_in, const int* in_sizes, int n_in,
                              void* d_out, int out_size)
{
    const float* X  = (const float*)d_in[0];
    const float* Wk = (const float*)d_in[1];
    const float* bk = (const float*)d_in[2];
    const float* Wq = (const float*)d_in[3];
    const float* bq = (const float*)d_in[4];
    const float* Wv = (const float*)d_in[5];
    const float* bv = (const float*)d_in[6];
    const float* Wo = (const float*)d_in[7];
    const float* bo = (const float*)d_in[8];
    float* out = (float*)d_out;

    transpose_w_kernel<<<dim3(128, 32), 256>>>(Wq, Wk, Wv, Wo);
    gemm_mma_kernel<0><<<dim3(24, 32), 256>>>(X, bq, bk, bv, nullptr, nullptr);
    attn_kernel<<<dim3(Sn / 64, Hn, Bn), 256>>>();
    gemm_mma_kernel<1><<<dim3(8, 32), 256>>>(nullptr, bo, nullptr, nullptr, X, out);
}

// round 4
// speedup vs baseline: 2.4913x; 1.5849x over previous
#include <cuda_runtime.h>
#include <cstdint>

#define Bn  4
#define Sn  1024
#define DMn 1024
#define Hn  16
#define DKn 64

// Scratch (allocation-free rule: __device__ globals)
__device__ float g_Q[(size_t)Bn * Hn * Sn * DKn];   // [b,h,s,k]
__device__ float g_K[(size_t)Bn * Hn * Sn * DKn];
__device__ float g_V[(size_t)Bn * Hn * Sn * DKn];
__device__ float g_Z[(size_t)Bn * Sn * Hn * DKn];   // [b,s,h*64+v]
// Transposed (K-major) weights, tf32-rounded:
//   n in [0,1024): Q | [1024,2048): K | [2048,3072): V | [3072,4096): Wo col
__device__ float g_Wt[(size_t)4096 * 1024];

__device__ __forceinline__ float to_tf32(float x) {
    uint32_t u;
    asm("cvt.rna.tf32.f32 %0, %1;" : "=r"(u) : "f"(x));
    return __uint_as_float(u);
}

__device__ __forceinline__ void mma_tf32(float* c, const uint32_t* a, const uint32_t* b) {
    asm volatile(
        "mma.sync.aligned.m16n8k8.row.col.f32.tf32.tf32.f32 "
        "{%0,%1,%2,%3}, {%4,%5,%6,%7}, {%8,%9}, {%0,%1,%2,%3};"
        : "+f"(c[0]), "+f"(c[1]), "+f"(c[2]), "+f"(c[3])
        : "r"(a[0]), "r"(a[1]), "r"(a[2]), "r"(a[3]), "r"(b[0]), "r"(b[1]));
}

// ---------------------------------------------------------------------------
// Kernel 0: pack weights transposed (K-major) + tf32-round.  grid=(128,32),256t
// ---------------------------------------------------------------------------
__global__ __launch_bounds__(256) void transpose_w_kernel(
    const float* __restrict__ Wq, const float* __restrict__ Wk,
    const float* __restrict__ Wv, const float* __restrict__ Wo)
{
    __shared__ float t[32][33];
    int n0 = blockIdx.x * 32;
    int d0 = blockIdx.y * 32;
    int r  = n0 >> 10;
    int tid = threadIdx.x;

    #pragma unroll
    for (int p = 0; p < 4; p++) {
        int idx = p * 256 + tid;
        int dl  = idx >> 5;
        int j   = idx & 31;
        int d   = d0 + dl;
        float v;
        if (r < 3) {
            int hh = (n0 >> 6) & 15;
            int k0 = n0 & 63;
            const float* W = (r == 0) ? Wq : (r == 1) ? Wk : Wv;
            v = W[(size_t)hh * 65536 + (size_t)d * 64 + k0 + j];
        } else {
            v = Wo[(size_t)d * 1024 + (n0 - 3072) + j];
        }
        t[dl][j] = v;
    }
    __syncthreads();
    #pragma unroll
    for (int p = 0; p < 4; p++) {
        int idx = p * 256 + tid;
        int nl  = idx >> 5;
        int dd  = idx & 31;
        g_Wt[(size_t)(n0 + nl) * 1024 + d0 + dd] = to_tf32(t[dd][nl]);
    }
}

// ---------------------------------------------------------------------------
// tf32 mma.sync GEMM (unchanged from R3, proven).
// ---------------------------------------------------------------------------
#define BKp 36

template <int MODE>
__global__ __launch_bounds__(256) void gemm_mma_kernel(
    const float* __restrict__ Ain,
    const float* __restrict__ b0, const float* __restrict__ b1,
    const float* __restrict__ b2,
    const float* __restrict__ Xres, float* __restrict__ Out)
{
    __shared__ float As[128 * BKp];
    __shared__ float Bs[128 * BKp];

    const int tid  = threadIdx.x;
    const int wid  = tid >> 5;
    const int lane = tid & 31;
    const int grp  = lane >> 2;
    const int tig  = lane & 3;
    const int wm   = wid & 1;
    const int wn   = wid >> 1;
    const int n0   = blockIdx.x * 128;
    const int m0   = blockIdx.y * 128;

    const float* A  = (MODE == 0) ? Ain : g_Z;
    const float* Bw = (MODE == 0) ? g_Wt : (g_Wt + (size_t)3072 * 1024);

    float acc[4][4][4];
    #pragma unroll
    for (int mt = 0; mt < 4; mt++)
        #pragma unroll
        for (int nt = 0; nt < 4; nt++)
            #pragma unroll
            for (int e = 0; e < 4; e++) acc[mt][nt][e] = 0.f;

    for (int kt = 0; kt < 1024; kt += 32) {
        #pragma unroll
        for (int it = 0; it < 4; it++) {
            int idx = it * 256 + tid;
            int row = idx >> 3;
            int c4  = idx & 7;
            float4 va = *reinterpret_cast<const float4*>(
                &A[(size_t)(m0 + row) * 1024 + kt + c4 * 4]);
            va.x = to_tf32(va.x); va.y = to_tf32(va.y);
            va.z = to_tf32(va.z); va.w = to_tf32(va.w);
            *reinterpret_cast<float4*>(&As[row * BKp + c4 * 4]) = va;
            float4 vb = *reinterpret_cast<const float4*>(
                &Bw[(size_t)(n0 + row) * 1024 + kt + c4 * 4]);
            *reinterpret_cast<float4*>(&Bs[row * BKp + c4 * 4]) = vb;
        }
        __syncthreads();

        #pragma unroll
        for (int ks = 0; ks < 4; ks++) {
            const int k = ks * 8;
            uint32_t bf[4][2];
            #pragma unroll
            for (int nt = 0; nt < 4; nt++) {
                int n = wn * 32 + nt * 8 + grp;
                bf[nt][0] = __float_as_uint(Bs[n * BKp + k + tig]);
                bf[nt][1] = __float_as_uint(Bs[n * BKp + k + tig + 4]);
            }
            #pragma unroll
            for (int mt = 0; mt < 4; mt++) {
                int r = wm * 64 + mt * 16 + grp;
                uint32_t af[4];
                af[0] = __float_as_uint(As[r * BKp + k + tig]);
                af[1] = __float_as_uint(As[(r + 8) * BKp + k + tig]);
                af[2] = __float_as_uint(As[r * BKp + k + tig + 4]);
                af[3] = __float_as_uint(As[(r + 8) * BKp + k + tig + 4]);
                #pragma unroll
                for (int nt = 0; nt < 4; nt++)
                    mma_tf32(acc[mt][nt], af, bf[nt]);
            }
        }
        __syncthreads();
    }

    #pragma unroll
    for (int nt = 0; nt < 4; nt++) {
        int n_base = n0 + wn * 32 + nt * 8;
        int ncol   = 2 * tig;
        if (MODE == 0) {
            int sel = n_base >> 10;
            int hh  = (n_base >> 6) & 15;
            int kk  = (n_base & 63) + ncol;
            const float* bias = (sel == 0) ? b0 : (sel == 1) ? b1 : b2;
            float* dst = (sel == 0) ? g_Q : (sel == 1) ? g_K : g_V;
            float bv0 = bias[hh * 64 + kk];
            float bv1 = bias[hh * 64 + kk + 1];
            #pragma unroll
            for (int mt = 0; mt < 4; mt++) {
                int r = m0 + wm * 64 + mt * 16 + grp;
                #pragma unroll
                for (int hrow = 0; hrow < 2; hrow++) {
                    int m  = r + hrow * 8;
                    int bb = m >> 10, ss = m & 1023;
                    float2 v;
                    v.x = acc[mt][nt][hrow * 2 + 0] + bv0;
                    v.y = acc[mt][nt][hrow * 2 + 1] + bv1;
                    *reinterpret_cast<float2*>(
                        &dst[((size_t)(bb * 16 + hh) * 1024 + ss) * 64 + kk]) = v;
                }
            }
        } else {
            int n  = n_base + ncol;
            float bv0 = b0[n], bv1 = b0[n + 1];
            #pragma unroll
            for (int mt = 0; mt < 4; mt++) {
                int r = m0 + wm * 64 + mt * 16 + grp;
                #pragma unroll
                for (int hrow = 0; hrow < 2; hrow++) {
                    int m = r + hrow * 8;
                    float2 xr = *reinterpret_cast<const float2*>(
                        &Xres[(size_t)m * 1024 + n]);
                    float2 v;
                    v.x = acc[mt][nt][hrow * 2 + 0] + bv0 + xr.x;
                    v.y = acc[mt][nt][hrow * 2 + 1] + bv1 + xr.y;
                    *reinterpret_cast<float2*>(&Out[(size_t)m * 1024 + n]) = v;
                }
            }
        }
    }
}

// ---------------------------------------------------------------------------
// Kernel 2: flash attention with mma.sync tf32.
// grid = (S/128, H, B), block 256 (8 warps). Warp owns 16 full q-rows.
// Dynamic smem: Ps[128*68] (Q staging, then per-warp P), Ks[64*68], Vt[64*68].
// ---------------------------------------------------------------------------
#define AStr 68
#define ATTN_SMEM ((128 + 64 + 64) * AStr * 4)

__global__ __launch_bounds__(256) void attn_mma_kernel()
{
    extern __shared__ float sm[];
    float* Ps = sm;                       // 128 x 68 (Q staging, then P)
    float* Ks = sm + 128 * AStr;          // 64 x 68 (K tile, K-major)
    float* Vt = Ks + 64 * AStr;           // 64 x 68 (V transposed [dv][key])

    const int q0 = blockIdx.x * 128;
    const int h  = blockIdx.y;
    const int b  = blockIdx.z;
    const int bh = b * Hn + h;

    const float* Qg = g_Q + (size_t)bh * Sn * DKn;
    const float* Kg = g_K + (size_t)bh * Sn * DKn;
    const float* Vg = g_V + (size_t)bh * Sn * DKn;

    const int tid  = threadIdx.x;
    const int wid  = tid >> 5;
    const int lane = tid & 31;
    const int grp  = lane >> 2;
    const int tig  = lane & 3;
    const int r0   = wid * 16;            // warp's 16 rows within the q-tile

    // Stage Q tile [128 x 64] into Ps
    #pragma unroll
    for (int it = 0; it < 8; it++) {
        int idx = it * 256 + tid;          // 0..2047
        int row = idx >> 4;                // 0..127
        int c4  = idx & 15;                // 0..15
        float4 v = *reinterpret_cast<const float4*>(
            &Qg[(size_t)(q0 + row) * DKn + c4 * 4]);
        *reinterpret_cast<float4*>(&Ps[row * AStr + c4 * 4]) = v;
    }
    __syncthreads();

    // Q fragments held in registers for all key tiles: qf[kk][4]
    uint32_t qf[8][4];
    #pragma unroll
    for (int kk = 0; kk < 8; kk++) {
        int k = kk * 8;
        qf[kk][0] = __float_as_uint(Ps[(r0 + grp)     * AStr + k + tig]);
        qf[kk][1] = __float_as_uint(Ps[(r0 + grp + 8) * AStr + k + tig]);
        qf[kk][2] = __float_as_uint(Ps[(r0 + grp)     * AStr + k + tig + 4]);
        qf[kk][3] = __float_as_uint(Ps[(r0 + grp + 8) * AStr + k + tig + 4]);
    }

    float m_i[2] = {-3.0e38f, -3.0e38f};
    float l_i[2] = {0.f, 0.f};
    float o[8][4];
    #pragma unroll
    for (int nt = 0; nt < 8; nt++)
        #pragma unroll
        for (int e = 0; e < 4; e++) o[nt][e] = 0.f;

    for (int t = 0; t < Sn; t += 64) {
        __syncthreads();   // previous tile's mma reads of Ks/Vt complete
        // K tile [64 x 64] natural (B-operand K-major)
        #pragma unroll
        for (int it = 0; it < 4; it++) {
            int idx = it * 256 + tid;      // 0..1023
            int row = idx >> 4;            // 0..63
            int c4  = idx & 15;
            float4 v = *reinterpret_cast<const float4*>(
                &Kg[(size_t)(t + row) * DKn + c4 * 4]);
            *reinterpret_cast<float4*>(&Ks[row * AStr + c4 * 4]) = v;
            // V tile transposed: Vt[dv][key]
            int key = idx & 63;
            int d4  = idx >> 6;            // 0..15
            float4 w = *reinterpret_cast<const float4*>(
                &Vg[(size_t)(t + key) * DKn + d4 * 4]);
            Vt[(d4 * 4 + 0) * AStr + key] = w.x;
            Vt[(d4 * 4 + 1) * AStr + key] = w.y;
            Vt[(d4 * 4 + 2) * AStr + key] = w.z;
            Vt[(d4 * 4 + 3) * AStr + key] = w.w;
        }
        __syncthreads();

        // S = Q K^T : warp computes 16 rows x 64 keys (nt = key octet)
        float s[8][4];
        #pragma unroll
        for (int nt = 0; nt < 8; nt++)
            #pragma unroll
            for (int e = 0; e < 4; e++) s[nt][e] = 0.f;

        #pragma unroll
        for (int kk = 0; kk < 8; kk++) {
            int k = kk * 8;
            #pragma unroll
            for (int nt = 0; nt < 8; nt++) {
                uint32_t bf[2];
                bf[0] = __float_as_uint(Ks[(nt * 8 + grp) * AStr + k + tig]);
                bf[1] = __float_as_uint(Ks[(nt * 8 + grp) * AStr + k + tig + 4]);
                mma_tf32(s[nt], qf[kk], bf);
            }
        }
        #pragma unroll
        for (int nt = 0; nt < 8; nt++)
            #pragma unroll
            for (int e = 0; e < 4; e++) s[nt][e] *= 0.125f;

        // Online softmax: row grp (elems 0,1), row grp+8 (elems 2,3)
        float rm0 = -3.0e38f, rm1 = -3.0e38f;
        #pragma unroll
        for (int nt = 0; nt < 8; nt++) {
            rm0 = fmaxf(rm0, fmaxf(s[nt][0], s[nt][1]));
            rm1 = fmaxf(rm1, fmaxf(s[nt][2], s[nt][3]));
        }
        rm0 = fmaxf(rm0, __shfl_xor_sync(0xffffffffu, rm0, 1));
        rm0 = fmaxf(rm0, __shfl_xor_sync(0xffffffffu, rm0, 2));
        rm1 = fmaxf(rm1, __shfl_xor_sync(0xffffffffu, rm1, 1));
        rm1 = fmaxf(rm1, __shfl_xor_sync(0xffffffffu, rm1, 2));

        float nm0 = fmaxf(m_i[0], rm0);
        float nm1 = fmaxf(m_i[1], rm1);
        float corr0 = __expf(m_i[0] - nm0);
        float corr1 = __expf(m_i[1] - nm1);
        m_i[0] = nm0; m_i[1] = nm1;

        float rs0 = 0.f, rs1 = 0.f;
        #pragma unroll
        for (int nt = 0; nt < 8; nt++) {
            s[nt][0] = __expf(s[nt][0] - nm0);
            s[nt][1] = __expf(s[nt][1] - nm0);
            s[nt][2] = __expf(s[nt][2] - nm1);
            s[nt][3] = __expf(s[nt][3] - nm1);
            rs0 += s[nt][0] + s[nt][1];
            rs1 += s[nt][2] + s[nt][3];
        }
        rs0 += __shfl_xor_sync(0xffffffffu, rs0, 1);
        rs0 += __shfl_xor_sync(0xffffffffu, rs0, 2);
        rs1 += __shfl_xor_sync(0xffffffffu, rs1, 1);
        rs1 += __shfl_xor_sync(0xffffffffu, rs1, 2);
        l_i[0] = l_i[0] * corr0 + rs0;
        l_i[1] = l_i[1] * corr1 + rs1;

        #pragma unroll
        for (int nt = 0; nt < 8; nt++) {
            o[nt][0] *= corr0; o[nt][1] *= corr0;
            o[nt][2] *= corr1; o[nt][3] *= corr1;
        }

        // Stage P into warp-private Ps rows (layout conversion C->A fragment)
        #pragma unroll
        for (int nt = 0; nt < 8; nt++) {
            *reinterpret_cast<float2*>(
                &Ps[(r0 + grp) * AStr + nt * 8 + 2 * tig]) =
                make_float2(s[nt][0], s[nt][1]);
            *reinterpret_cast<float2*>(
                &Ps[(r0 + grp + 8) * AStr + nt * 8 + 2 * tig]) =
                make_float2(s[nt][2], s[nt][3]);
        }
        __syncwarp();

        // O += P V : K-dim = 64 keys, N-dim = 64 dv
        #pragma unroll
        for (int kk = 0; kk < 8; kk++) {
            int k = kk * 8;
            uint32_t af[4];
            af[0] = __float_as_uint(Ps[(r0 + grp)     * AStr + k + tig]);
            af[1] = __float_as_uint(Ps[(r0 + grp + 8) * AStr + k + tig]);
            af[2] = __float_as_uint(Ps[(r0 + grp)     * AStr + k + tig + 4]);
            af[3] = __float_as_uint(Ps[(r0 + grp + 8) * AStr + k + tig + 4]);
            #pragma unroll
            for (int nt = 0; nt < 8; nt++) {
                uint32_t bf[2];
                bf[0] = __float_as_uint(Vt[(nt * 8 + grp) * AStr + k + tig]);
                bf[1] = __float_as_uint(Vt[(nt * 8 + grp) * AStr + k + tig + 4]);
                mma_tf32(o[nt], af, bf);
            }
        }
    }

    // Epilogue: normalize and write to concat layout g_Z[b, s, h*64+dv]
    float inv0 = 1.0f / l_i[0];
    float inv1 = 1.0f / l_i[1];
    int row0 = q0 + r0 + grp;
    #pragma unroll
    for (int nt = 0; nt < 8; nt++) {
        int col = h * 64 + nt * 8 + 2 * tig;
        *reinterpret_cast<float2*>(
            &g_Z[((size_t)b * Sn + row0) * 1024 + col]) =
            make_float2(o[nt][0] * inv0, o[nt][1] * inv0);
        *reinterpret_cast<float2*>(
            &g_Z[((size_t)b * Sn + row0 + 8) * 1024 + col]) =
            make_float2(o[nt][2] * inv1, o[nt][3] * inv1);
    }
}

// ---------------------------------------------------------------------------
extern "C" void kernel_launch(void* const* d_in, const int* in_sizes, int n_in,
                              void* d_out, int out_size)
{
    const float* X  = (const float*)d_in[0];
    const float* Wk = (const float*)d_in[1];
    const float* bk = (const float*)d_in[2];
    const float* Wq = (const float*)d_in[3];
    const float* bq = (const float*)d_in[4];
    const float* Wv = (const float*)d_in[5];
    const float* bv = (const float*)d_in[6];
    const float* Wo = (const float*)d_in[7];
    const float* bo = (const float*)d_in[8];
    float* out = (float*)d_out;

    cudaFuncSetAttribute(attn_mma_kernel,
                         cudaFuncAttributeMaxDynamicSharedMemorySize, ATTN_SMEM);

    transpose_w_kernel<<<dim3(128, 32), 256>>>(Wq, Wk, Wv, Wo);
    gemm_mma_kernel<0><<<dim3(24, 32), 256>>>(X, bq, bk, bv, nullptr, nullptr);
    attn_mma_kernel<<<dim3(Sn / 128, Hn, Bn), 256, ATTN_SMEM>>>();
    gemm_mma_kernel<1><<<dim3(8, 32), 256>>>(nullptr, bo, nullptr, nullptr, X, out);
}

// round 5
// speedup vs baseline: 3.0418x; 1.2210x over previous
#include <cuda_runtime.h>
#include <cstdint>

#define Bn  4
#define Sn  1024
#define DMn 1024
#define Hn  16
#define DKn 64

// Scratch (allocation-free rule: __device__ globals)
__device__ float g_Q[(size_t)Bn * Hn * Sn * DKn];   // [b,h,s,k]
__device__ float g_K[(size_t)Bn * Hn * Sn * DKn];
__device__ float g_V[(size_t)Bn * Hn * Sn * DKn];
__device__ float g_Z[(size_t)Bn * Sn * Hn * DKn];   // [b,s,h*64+v]
// Transposed (K-major) weights, tf32-rounded:
//   n in [0,1024): Q | [1024,2048): K | [2048,3072): V | [3072,4096): Wo col
__device__ float g_Wt[(size_t)4096 * 1024];

__device__ __forceinline__ float to_tf32(float x) {
    uint32_t u;
    asm("cvt.rna.tf32.f32 %0, %1;" : "=r"(u) : "f"(x));
    return __uint_as_float(u);
}
__device__ __forceinline__ uint32_t smem_u32(const void* p) {
    uint32_t a;
    asm("{ .reg .u64 t; cvta.to.shared.u64 t, %1; cvt.u32.u64 %0, t; }"
        : "=r"(a) : "l"(p));
    return a;
}
__device__ __forceinline__ void cp16(uint32_t dst, const void* src) {
    asm volatile("cp.async.cg.shared.global [%0], [%1], 16;"
                 :: "r"(dst), "l"(src));
}
__device__ __forceinline__ void cp_commit() {
    asm volatile("cp.async.commit_group;");
}
template <int N>
__device__ __forceinline__ void cp_wait() {
    asm volatile("cp.async.wait_group %0;" :: "n"(N));
}

__device__ __forceinline__ void mma_tf32(float* c, const uint32_t* a, const uint32_t* b) {
    asm volatile(
        "mma.sync.aligned.m16n8k8.row.col.f32.tf32.tf32.f32 "
        "{%0,%1,%2,%3}, {%4,%5,%6,%7}, {%8,%9}, {%0,%1,%2,%3};"
        : "+f"(c[0]), "+f"(c[1]), "+f"(c[2]), "+f"(c[3])
        : "r"(a[0]), "r"(a[1]), "r"(a[2]), "r"(a[3]), "r"(b[0]), "r"(b[1]));
}

// ---------------------------------------------------------------------------
// Kernel 0: pack weights transposed (K-major) + tf32-round.  grid=(128,32),256t
// ---------------------------------------------------------------------------
__global__ __launch_bounds__(256) void transpose_w_kernel(
    const float* __restrict__ Wq, const float* __restrict__ Wk,
    const float* __restrict__ Wv, const float* __restrict__ Wo)
{
    __shared__ float t[32][33];
    int n0 = blockIdx.x * 32;
    int d0 = blockIdx.y * 32;
    int r  = n0 >> 10;
    int tid = threadIdx.x;

    #pragma unroll
    for (int p = 0; p < 4; p++) {
        int idx = p * 256 + tid;
        int dl  = idx >> 5;
        int j   = idx & 31;
        int d   = d0 + dl;
        float v;
        if (r < 3) {
            int hh = (n0 >> 6) & 15;
            int k0 = n0 & 63;
            const float* W = (r == 0) ? Wq : (r == 1) ? Wk : Wv;
            v = W[(size_t)hh * 65536 + (size_t)d * 64 + k0 + j];
        } else {
            v = Wo[(size_t)d * 1024 + (n0 - 3072) + j];
        }
        t[dl][j] = v;
    }
    __syncthreads();
    #pragma unroll
    for (int p = 0; p < 4; p++) {
        int idx = p * 256 + tid;
        int nl  = idx >> 5;
        int dd  = idx & 31;
        g_Wt[(size_t)(n0 + nl) * 1024 + d0 + dd] = to_tf32(t[dd][nl]);
    }
}

// ---------------------------------------------------------------------------
// tf32 mma.sync GEMM with 2-stage cp.async pipeline.
// C[4096, NG] = A[4096,1024] @ Wt[NG,1024]^T.  BM=128,BN=128,BK=32, 8 warps.
// ---------------------------------------------------------------------------
#define BKp 36
#define GEMM_SMEM (4 * 128 * BKp * 4)

template <int MODE>
__global__ __launch_bounds__(256, 2) void gemm_mma_kernel(
    const float* __restrict__ Ain,
    const float* __restrict__ b0, const float* __restrict__ b1,
    const float* __restrict__ b2,
    const float* __restrict__ Xres, float* __restrict__ Out)
{
    extern __shared__ float smn[];
    float* AsBuf = smn;                    // 2 x 128*BKp
    float* BsBuf = smn + 2 * 128 * BKp;    // 2 x 128*BKp
    const uint32_t sA0 = smem_u32(AsBuf);
    const uint32_t sB0 = smem_u32(BsBuf);
    const uint32_t bufBytes = 128 * BKp * 4;

    const int tid  = threadIdx.x;
    const int wid  = tid >> 5;
    const int lane = tid & 31;
    const int grp  = lane >> 2;
    const int tig  = lane & 3;
    const int wm   = wid & 1;
    const int wn   = wid >> 1;
    const int n0   = blockIdx.x * 128;
    const int m0   = blockIdx.y * 128;

    const float* A  = (MODE == 0) ? Ain : g_Z;
    const float* Bw = (MODE == 0) ? g_Wt : (g_Wt + (size_t)3072 * 1024);

    // Per-thread copy mapping: 4 x 16B for A, 4 x 16B for B per stage
    const float* srcA[4];
    const float* srcB[4];
    uint32_t dstOff[4];
    #pragma unroll
    for (int i = 0; i < 4; i++) {
        int idx = i * 256 + tid;       // 0..1023
        int row = idx >> 3;            // 0..127
        int c4  = idx & 7;             // 0..7
        srcA[i] = A  + (size_t)(m0 + row) * 1024 + c4 * 4;
        srcB[i] = Bw + (size_t)(n0 + row) * 1024 + c4 * 4;
        dstOff[i] = (uint32_t)(row * BKp + c4 * 4) * 4;
    }

    float acc[4][4][4];
    #pragma unroll
    for (int mt = 0; mt < 4; mt++)
        #pragma unroll
        for (int nt = 0; nt < 4; nt++)
            #pragma unroll
            for (int e = 0; e < 4; e++) acc[mt][nt][e] = 0.f;

    // Prologue: stage chunk 0 into buffer 0
    #pragma unroll
    for (int i = 0; i < 4; i++) {
        cp16(sA0 + dstOff[i], srcA[i]);
        cp16(sB0 + dstOff[i], srcB[i]);
    }
    cp_commit();

    for (int ch = 0; ch < 32; ch++) {
        if (ch < 31) {
            int kt = (ch + 1) * 32;
            uint32_t boff = ((ch + 1) & 1) * bufBytes;
            #pragma unroll
            for (int i = 0; i < 4; i++) {
                cp16(sA0 + boff + dstOff[i], srcA[i] + kt);
                cp16(sB0 + boff + dstOff[i], srcB[i] + kt);
            }
            cp_commit();
            cp_wait<1>();
        } else {
            cp_wait<0>();
        }
        __syncthreads();

        const float* As = AsBuf + (ch & 1) * 128 * BKp;
        const float* Bs = BsBuf + (ch & 1) * 128 * BKp;

        #pragma unroll
        for (int ks = 0; ks < 4; ks++) {
            const int k = ks * 8;
            uint32_t bf[4][2];
            #pragma unroll
            for (int nt = 0; nt < 4; nt++) {
                int n = wn * 32 + nt * 8 + grp;
                bf[nt][0] = __float_as_uint(Bs[n * BKp + k + tig]);
                bf[nt][1] = __float_as_uint(Bs[n * BKp + k + tig + 4]);
            }
            #pragma unroll
            for (int mt = 0; mt < 4; mt++) {
                int r = wm * 64 + mt * 16 + grp;
                uint32_t af[4];
                af[0] = __float_as_uint(As[r * BKp + k + tig]);
                af[1] = __float_as_uint(As[(r + 8) * BKp + k + tig]);
                af[2] = __float_as_uint(As[r * BKp + k + tig + 4]);
                af[3] = __float_as_uint(As[(r + 8) * BKp + k + tig + 4]);
                #pragma unroll
                for (int nt = 0; nt < 4; nt++)
                    mma_tf32(acc[mt][nt], af, bf[nt]);
            }
        }
        __syncthreads();
    }

    // Epilogue: direct fragment stores
    #pragma unroll
    for (int nt = 0; nt < 4; nt++) {
        int n_base = n0 + wn * 32 + nt * 8;
        int ncol   = 2 * tig;
        if (MODE == 0) {
            int sel = n_base >> 10;
            int hh  = (n_base >> 6) & 15;
            int kk  = (n_base & 63) + ncol;
            const float* bias = (sel == 0) ? b0 : (sel == 1) ? b1 : b2;
            float* dst = (sel == 0) ? g_Q : (sel == 1) ? g_K : g_V;
            float bv0 = bias[hh * 64 + kk];
            float bv1 = bias[hh * 64 + kk + 1];
            #pragma unroll
            for (int mt = 0; mt < 4; mt++) {
                int r = m0 + wm * 64 + mt * 16 + grp;
                #pragma unroll
                for (int hrow = 0; hrow < 2; hrow++) {
                    int m  = r + hrow * 8;
                    int bb = m >> 10, ss = m & 1023;
                    float2 v;
                    v.x = acc[mt][nt][hrow * 2 + 0] + bv0;
                    v.y = acc[mt][nt][hrow * 2 + 1] + bv1;
                    *reinterpret_cast<float2*>(
                        &dst[((size_t)(bb * 16 + hh) * 1024 + ss) * 64 + kk]) = v;
                }
            }
        } else {
            int n  = n_base + ncol;
            float bv0 = b0[n], bv1 = b0[n + 1];
            #pragma unroll
            for (int mt = 0; mt < 4; mt++) {
                int r = m0 + wm * 64 + mt * 16 + grp;
                #pragma unroll
                for (int hrow = 0; hrow < 2; hrow++) {
                    int m = r + hrow * 8;
                    float2 xr = *reinterpret_cast<const float2*>(
                        &Xres[(size_t)m * 1024 + n]);
                    float2 v;
                    v.x = acc[mt][nt][hrow * 2 + 0] + bv0 + xr.x;
                    v.y = acc[mt][nt][hrow * 2 + 1] + bv1 + xr.y;
                    *reinterpret_cast<float2*>(&Out[(size_t)m * 1024 + n]) = v;
                }
            }
        }
    }
}

// ---------------------------------------------------------------------------
// Kernel 2: flash attention, mma.sync tf32 + cp.async double-buffered K/V.
// grid = (S/128, H, B), block 256 (8 warps). Warp owns 16 full q-rows.
// V kept in NATURAL [key][dv] layout; PV B-fragments read directly from it.
// ---------------------------------------------------------------------------
#define AStr 68
#define ATTN_SMEM ((128 + 4 * 64) * AStr * 4)

__global__ __launch_bounds__(256, 2) void attn_mma_kernel()
{
    extern __shared__ float sm[];
    float* Ps    = sm;                        // 128 x 68 (Q staging, then P)
    float* KsBuf = sm + 128 * AStr;           // 2 x 64 x 68
    float* VsBuf = KsBuf + 2 * 64 * AStr;     // 2 x 64 x 68 (natural layout)
    const uint32_t sK0 = smem_u32(KsBuf);
    const uint32_t sV0 = smem_u32(VsBuf);
    const uint32_t tileBytes = 64 * AStr * 4;

    const int q0 = blockIdx.x * 128;
    const int h  = blockIdx.y;
    const int b  = blockIdx.z;
    const int bh = b * Hn + h;

    const float* Qg = g_Q + (size_t)bh * Sn * DKn;
    const float* Kg = g_K + (size_t)bh * Sn * DKn;
    const float* Vg = g_V + (size_t)bh * Sn * DKn;

    const int tid  = threadIdx.x;
    const int wid  = tid >> 5;
    const int lane = tid & 31;
    const int grp  = lane >> 2;
    const int tig  = lane & 3;
    const int r0   = wid * 16;

    // Per-thread K/V copy mapping: 4 x 16B each per tile
    const float* srcK[4];
    const float* srcV[4];
    uint32_t dstKV[4];
    #pragma unroll
    for (int i = 0; i < 4; i++) {
        int idx = i * 256 + tid;       // 0..1023
        int row = idx >> 4;            // 0..63
        int c4  = idx & 15;            // 0..15
        srcK[i] = Kg + (size_t)row * DKn + c4 * 4;
        srcV[i] = Vg + (size_t)row * DKn + c4 * 4;
        dstKV[i] = (uint32_t)(row * AStr + c4 * 4) * 4;
    }

    // Prologue: stage K/V tile 0 into buffer 0
    #pragma unroll
    for (int i = 0; i < 4; i++) {
        cp16(sK0 + dstKV[i], srcK[i]);
        cp16(sV0 + dstKV[i], srcV[i]);
    }
    cp_commit();

    // Stage Q tile [128 x 64] into Ps (regular loads, one-time)
    #pragma unroll
    for (int it = 0; it < 8; it++) {
        int idx = it * 256 + tid;
        int row = idx >> 4;
        int c4  = idx & 15;
        float4 v = *reinterpret_cast<const float4*>(
            &Qg[(size_t)(q0 + row) * DKn + c4 * 4]);
        *reinterpret_cast<float4*>(&Ps[row * AStr + c4 * 4]) = v;
    }
    __syncthreads();

    uint32_t qf[8][4];
    #pragma unroll
    for (int kk = 0; kk < 8; kk++) {
        int k = kk * 8;
        qf[kk][0] = __float_as_uint(Ps[(r0 + grp)     * AStr + k + tig]);
        qf[kk][1] = __float_as_uint(Ps[(r0 + grp + 8) * AStr + k + tig]);
        qf[kk][2] = __float_as_uint(Ps[(r0 + grp)     * AStr + k + tig + 4]);
        qf[kk][3] = __float_as_uint(Ps[(r0 + grp + 8) * AStr + k + tig + 4]);
    }
    __syncthreads();   // Ps free for P staging

    float m_i[2] = {-3.0e38f, -3.0e38f};
    float l_i[2] = {0.f, 0.f};
    float o[8][4];
    #pragma unroll
    for (int nt = 0; nt < 8; nt++)
        #pragma unroll
        for (int e = 0; e < 4; e++) o[nt][e] = 0.f;

    for (int ti = 0; ti < 16; ti++) {
        if (ti < 15) {
            int off = (ti + 1) * 64 * DKn;
            uint32_t boff = ((ti + 1) & 1) * tileBytes;
            #pragma unroll
            for (int i = 0; i < 4; i++) {
                cp16(sK0 + boff + dstKV[i], srcK[i] + off);
                cp16(sV0 + boff + dstKV[i], srcV[i] + off);
            }
            cp_commit();
            cp_wait<1>();
        } else {
            cp_wait<0>();
        }
        __syncthreads();

        const float* Ks = KsBuf + (ti & 1) * 64 * AStr;
        const float* Vs = VsBuf + (ti & 1) * 64 * AStr;

        // S = Q K^T
        float s[8][4];
        #pragma unroll
        for (int nt = 0; nt < 8; nt++)
            #pragma unroll
            for (int e = 0; e < 4; e++) s[nt][e] = 0.f;

        #pragma unroll
        for (int kk = 0; kk < 8; kk++) {
            int k = kk * 8;
            #pragma unroll
            for (int nt = 0; nt < 8; nt++) {
                uint32_t bf[2];
                bf[0] = __float_as_uint(Ks[(nt * 8 + grp) * AStr + k + tig]);
                bf[1] = __float_as_uint(Ks[(nt * 8 + grp) * AStr + k + tig + 4]);
                mma_tf32(s[nt], qf[kk], bf);
            }
        }
        #pragma unroll
        for (int nt = 0; nt < 8; nt++)
            #pragma unroll
            for (int e = 0; e < 4; e++) s[nt][e] *= 0.125f;

        // Online softmax
        float rm0 = -3.0e38f, rm1 = -3.0e38f;
        #pragma unroll
        for (int nt = 0; nt < 8; nt++) {
            rm0 = fmaxf(rm0, fmaxf(s[nt][0], s[nt][1]));
            rm1 = fmaxf(rm1, fmaxf(s[nt][2], s[nt][3]));
        }
        rm0 = fmaxf(rm0, __shfl_xor_sync(0xffffffffu, rm0, 1));
        rm0 = fmaxf(rm0, __shfl_xor_sync(0xffffffffu, rm0, 2));
        rm1 = fmaxf(rm1, __shfl_xor_sync(0xffffffffu, rm1, 1));
        rm1 = fmaxf(rm1, __shfl_xor_sync(0xffffffffu, rm1, 2));

        float nm0 = fmaxf(m_i[0], rm0);
        float nm1 = fmaxf(m_i[1], rm1);
        float corr0 = __expf(m_i[0] - nm0);
        float corr1 = __expf(m_i[1] - nm1);
        m_i[0] = nm0; m_i[1] = nm1;

        float rs0 = 0.f, rs1 = 0.f;
        #pragma unroll
        for (int nt = 0; nt < 8; nt++) {
            s[nt][0] = __expf(s[nt][0] - nm0);
            s[nt][1] = __expf(s[nt][1] - nm0);
            s[nt][2] = __expf(s[nt][2] - nm1);
            s[nt][3] = __expf(s[nt][3] - nm1);
            rs0 += s[nt][0] + s[nt][1];
            rs1 += s[nt][2] + s[nt][3];
        }
        rs0 += __shfl_xor_sync(0xffffffffu, rs0, 1);
        rs0 += __shfl_xor_sync(0xffffffffu, rs0, 2);
        rs1 += __shfl_xor_sync(0xffffffffu, rs1, 1);
        rs1 += __shfl_xor_sync(0xffffffffu, rs1, 2);
        l_i[0] = l_i[0] * corr0 + rs0;
        l_i[1] = l_i[1] * corr1 + rs1;

        #pragma unroll
        for (int nt = 0; nt < 8; nt++) {
            o[nt][0] *= corr0; o[nt][1] *= corr0;
            o[nt][2] *= corr1; o[nt][3] *= corr1;
        }

        // Stage P (warp-private Ps rows): accumulator layout -> A-fragment
        #pragma unroll
        for (int nt = 0; nt < 8; nt++) {
            *reinterpret_cast<float2*>(
                &Ps[(r0 + grp) * AStr + nt * 8 + 2 * tig]) =
                make_float2(s[nt][0], s[nt][1]);
            *reinterpret_cast<float2*>(
                &Ps[(r0 + grp + 8) * AStr + nt * 8 + 2 * tig]) =
                make_float2(s[nt][2], s[nt][3]);
        }
        __syncwarp();

        // O += P V, B-fragments straight from natural V[key][dv]
        #pragma unroll
        for (int kk = 0; kk < 8; kk++) {
            int k = kk * 8;
            uint32_t af[4];
            af[0] = __float_as_uint(Ps[(r0 + grp)     * AStr + k + tig]);
            af[1] = __float_as_uint(Ps[(r0 + grp + 8) * AStr + k + tig]);
            af[2] = __float_as_uint(Ps[(r0 + grp)     * AStr + k + tig + 4]);
            af[3] = __float_as_uint(Ps[(r0 + grp + 8) * AStr + k + tig + 4]);
            #pragma unroll
            for (int nt = 0; nt < 8; nt++) {
                uint32_t bf[2];
                bf[0] = __float_as_uint(Vs[(k + tig)     * AStr + nt * 8 + grp]);
                bf[1] = __float_as_uint(Vs[(k + tig + 4) * AStr + nt * 8 + grp]);
                mma_tf32(o[nt], af, bf);
            }
        }
        __syncthreads();
    }

    // Epilogue: normalize, write concat layout g_Z[b, s, h*64+dv]
    float inv0 = 1.0f / l_i[0];
    float inv1 = 1.0f / l_i[1];
    int row0 = q0 + r0 + grp;
    #pragma unroll
    for (int nt = 0; nt < 8; nt++) {
        int col = h * 64 + nt * 8 + 2 * tig;
        *reinterpret_cast<float2*>(
            &g_Z[((size_t)b * Sn + row0) * 1024 + col]) =
            make_float2(o[nt][0] * inv0, o[nt][1] * inv0);
        *reinterpret_cast<float2*>(
            &g_Z[((size_t)b * Sn + row0 + 8) * 1024 + col]) =
            make_float2(o[nt][2] * inv1, o[nt][3] * inv1);
    }
}

// ---------------------------------------------------------------------------
extern "C" void kernel_launch(void* const* d_in, const int* in_sizes, int n_in,
                              void* d_out, int out_size)
{
    const float* X  = (const float*)d_in[0];
    const float* Wk = (const float*)d_in[1];
    const float* bk = (const float*)d_in[2];
    const float* Wq = (const float*)d_in[3];
    const float* bq = (const float*)d_in[4];
    const float* Wv = (const float*)d_in[5];
    const float* bv = (const float*)d_in[6];
    const float* Wo = (const float*)d_in[7];
    const float* bo = (const float*)d_in[8];
    float* out = (float*)d_out;

    cudaFuncSetAttribute(gemm_mma_kernel<0>,
                         cudaFuncAttributeMaxDynamicSharedMemorySize, GEMM_SMEM);
    cudaFuncSetAttribute(gemm_mma_kernel<1>,
                         cudaFuncAttributeMaxDynamicSharedMemorySize, GEMM_SMEM);
    cudaFuncSetAttribute(attn_mma_kernel,
                         cudaFuncAttributeMaxDynamicSharedMemorySize, ATTN_SMEM);

    transpose_w_kernel<<<dim3(128, 32), 256>>>(Wq, Wk, Wv, Wo);
    gemm_mma_kernel<0><<<dim3(24, 32), 256, GEMM_SMEM>>>(
        X, bq, bk, bv, nullptr, nullptr);
    attn_mma_kernel<<<dim3(Sn / 128, Hn, Bn), 256, ATTN_SMEM>>>();
    gemm_mma_kernel<1><<<dim3(8, 32), 256, GEMM_SMEM>>>(
        nullptr, bo, nullptr, nullptr, X, out);
}